// round 1
// baseline (speedup 1.0000x reference)
#include <cuda_runtime.h>
#include <math_constants.h>

// Problem constants (fixed by the dataset): B=8, N=M=8192, 3-D points.
#define MAXB 8
#define MAXN 8192
#define MAXM 8192
#define SBLK 128            // sources per block
#define NSBLK (MAXN / SBLK) // 64 source blocks per batch

// Static scratch (allocation-free rule): packed float4 points, target mins, per-block source sums.
__device__ float4       g_src4[MAXB * MAXN];
__device__ float4       g_tgt4[MAXB * MAXM];
__device__ unsigned int g_tmin[MAXB * MAXM];
__device__ float        g_ssum[MAXB * NSBLK];

// ---------------------------------------------------------------------------
// Kernel 1: pack [*,3] float points into float4 (x,y,z,0) and init tmin to +inf
// ---------------------------------------------------------------------------
__global__ void chamfer_prep(const float* __restrict__ src,
                             const float* __restrict__ tgt,
                             int BN, int BM) {
    int i = blockIdx.x * blockDim.x + threadIdx.x;
    if (i < BN) {
        g_src4[i] = make_float4(src[3 * i], src[3 * i + 1], src[3 * i + 2], 0.0f);
    }
    if (i < BM) {
        g_tgt4[i] = make_float4(tgt[3 * i], tgt[3 * i + 1], tgt[3 * i + 2], 0.0f);
        g_tmin[i] = 0x7f800000u;  // +inf
    }
}

// ---------------------------------------------------------------------------
// Kernel 2: fused pairwise min pass.
// Block = 256 threads = 16 target-groups (tx) x 16 source-groups (ty).
// Each block owns 128 sources and scans all M targets in chunks of 128.
// Thread micro-tile: 8 sources (registers, persistent) x 8 targets (per chunk).
//  - source mins: complete within block (registers) -> deterministic block sum.
//  - target mins: half-warp shuffle reduce over the 16 ty-lanes -> global RED.MIN.
// ---------------------------------------------------------------------------
__global__ void __launch_bounds__(256, 2)
chamfer_main(int N, int M) {
    const int b    = blockIdx.y;
    const int sblk = blockIdx.x;
    const int tid  = threadIdx.x;
    const int tx   = tid >> 4;    // target group 0..15
    const int ty   = tid & 15;    // source group 0..15 (consecutive lanes!)

    const float4* __restrict__ S = g_src4 + (size_t)b * N + sblk * SBLK;
    const float4* __restrict__ T = g_tgt4 + (size_t)b * M;

    float sx[8], sy[8], sz[8], smin[8];
#pragma unroll
    for (int i = 0; i < 8; i++) {
        float4 v = S[ty * 8 + i];
        sx[i] = v.x; sy[i] = v.y; sz[i] = v.z;
        smin[i] = CUDART_INF_F;
    }

    for (int c = 0; c < M; c += 128) {
        float4 t[8];
#pragma unroll
        for (int j = 0; j < 8; j++) t[j] = T[c + tx * 8 + j];

#pragma unroll
        for (int j = 0; j < 8; j++) {
            float tmj = CUDART_INF_F;
            const float px = t[j].x, py = t[j].y, pz = t[j].z;
#pragma unroll
            for (int i = 0; i < 8; i++) {
                float dx = sx[i] - px;
                float dy = sy[i] - py;
                float dz = sz[i] - pz;
                float d  = dx * dx;
                d = fmaf(dy, dy, d);
                d = fmaf(dz, dz, d);
                smin[i] = fminf(smin[i], d);
                tmj     = fminf(tmj, d);
            }
            // Reduce over the 16 consecutive ty-lanes (half warp).
            tmj = fminf(tmj, __shfl_xor_sync(0xffffffffu, tmj, 8, 16));
            tmj = fminf(tmj, __shfl_xor_sync(0xffffffffu, tmj, 4, 16));
            tmj = fminf(tmj, __shfl_xor_sync(0xffffffffu, tmj, 2, 16));
            tmj = fminf(tmj, __shfl_xor_sync(0xffffffffu, tmj, 1, 16));
            if (ty == 0) {
                atomicMin(&g_tmin[(size_t)b * M + c + tx * 8 + j],
                          __float_as_uint(tmj));  // emits RED (no return use)
            }
        }
    }

    // Finalize source mins: reduce across the 16 tx target-slices, then block-sum.
    __shared__ float red[16][136];  // padded to keep column reads conflict-free
#pragma unroll
    for (int i = 0; i < 8; i++) red[tx][ty * 8 + i] = smin[i];
    __syncthreads();

    __shared__ float partial[128];
    if (tid < 128) {
        float m = red[0][tid];
#pragma unroll
        for (int k = 1; k < 16; k++) m = fminf(m, red[k][tid]);
        partial[tid] = m;
    }
    __syncthreads();
    if (tid < 64) partial[tid] += partial[tid + 64];
    __syncthreads();
    if (tid < 32) {
        float v = partial[tid] + partial[tid + 32];
#pragma unroll
        for (int o = 16; o > 0; o >>= 1)
            v += __shfl_down_sync(0xffffffffu, v, o);
        if (tid == 0) g_ssum[b * gridDim.x + sblk] = v;  // deterministic write
    }
}

// ---------------------------------------------------------------------------
// Kernel 3: deterministic final reduction. One block per batch.
// out[b] = mean_t(tmin) + mean_s(smin)
// ---------------------------------------------------------------------------
__global__ void chamfer_finish(float* __restrict__ out, int N, int M, int nsblk) {
    const int b   = blockIdx.x;
    const int tid = threadIdx.x;  // 256 threads

    float ts = 0.0f;
    for (int i = tid; i < M; i += 256)
        ts += __uint_as_float(g_tmin[(size_t)b * M + i]);
    float ss = 0.0f;
    for (int i = tid; i < nsblk; i += 256)
        ss += g_ssum[b * nsblk + i];

    __shared__ float s1[256], s2[256];
    s1[tid] = ts; s2[tid] = ss;
    __syncthreads();
    for (int o = 128; o > 0; o >>= 1) {
        if (tid < o) { s1[tid] += s1[tid + o]; s2[tid] += s2[tid + o]; }
        __syncthreads();
    }
    if (tid == 0) out[b] = s1[0] / (float)M + s2[0] / (float)N;
}

// ---------------------------------------------------------------------------
extern "C" void kernel_launch(void* const* d_in, const int* in_sizes, int n_in,
                              void* d_out, int out_size) {
    const float* src = (const float*)d_in[0];
    const float* tgt = (const float*)d_in[1];
    float* out = (float*)d_out;

    const int B = out_size;                 // 8
    const int N = in_sizes[0] / (3 * B);    // 8192
    const int M = in_sizes[1] / (3 * B);    // 8192
    const int BN = B * N, BM = B * M;
    const int total = BN > BM ? BN : BM;

    chamfer_prep<<<(total + 255) / 256, 256>>>(src, tgt, BN, BM);

    dim3 grid(N / SBLK, B);
    chamfer_main<<<grid, 256>>>(N, M);

    chamfer_finish<<<B, 256>>>(out, N, M, N / SBLK);
}

// round 2
// speedup vs baseline: 1.1264x; 1.1264x over previous
#include <cuda_runtime.h>
#include <math_constants.h>

// Problem constants (fixed by the dataset): B=8, N=M=8192, 3-D points.
#define MAXB 8
#define MAXN 8192
#define MAXM 8192
#define SBLK 128            // sources per block
#define NSBLK (MAXN / SBLK) // 64 source blocks per batch

typedef unsigned long long u64;

// Static scratch (allocation-free rule).
__device__ float4       g_srcp[MAXB * MAXN];      // {x, y, z, -0.5|s|^2}
__device__ float4       g_ta[MAXB * MAXM / 2];    // {x0, x1, y0, y1} per target pair
__device__ float4       g_tb[MAXB * MAXM / 2];    // {z0, z1, k0, k1} per target pair
__device__ unsigned int g_tmin[MAXB * MAXM];      // monotonic-encoded min distance
__device__ float        g_ssum[MAXB * NSBLK];

// ---- f32x2 packed math (FFMA2/FADD2 — PTX-only on sm_103a) --------------
__device__ __forceinline__ u64 pack2(float lo, float hi) {
    u64 r; asm("mov.b64 %0,{%1,%2};" : "=l"(r) : "f"(lo), "f"(hi)); return r;
}
__device__ __forceinline__ void unpack2(u64 v, float& lo, float& hi) {
    asm("mov.b64 {%0,%1},%2;" : "=f"(lo), "=f"(hi) : "l"(v));
}
__device__ __forceinline__ u64 fma2_(u64 a, u64 b, u64 c) {
    u64 d; asm("fma.rn.f32x2 %0,%1,%2,%3;" : "=l"(d) : "l"(a), "l"(b), "l"(c)); return d;
}
__device__ __forceinline__ u64 add2_(u64 a, u64 b) {
    u64 d; asm("add.rn.f32x2 %0,%1,%2;" : "=l"(d) : "l"(a), "l"(b)); return d;
}

// ---- monotonic float<->uint encoding (atomicMin-safe for any sign) ------
__device__ __forceinline__ unsigned fenc(float f) {
    unsigned b = __float_as_uint(f);
    return (b & 0x80000000u) ? ~b : (b | 0x80000000u);
}
__device__ __forceinline__ float fdec(unsigned k) {
    return __uint_as_float((k & 0x80000000u) ? (k & 0x7fffffffu) : ~k);
}

// ---------------------------------------------------------------------------
// Kernel 1: pack sources {x,y,z,k}, target PAIRS into f32x2-friendly SoA,
// and init tmin to encoded +inf.
// ---------------------------------------------------------------------------
__global__ void chamfer_prep(const float* __restrict__ src,
                             const float* __restrict__ tgt,
                             int BN, int BM) {
    int i = blockIdx.x * blockDim.x + threadIdx.x;
    if (i < BN) {
        float x = src[3 * i], y = src[3 * i + 1], z = src[3 * i + 2];
        float k = -0.5f * (x * x + y * y + z * z);
        g_srcp[i] = make_float4(x, y, z, k);
    }
    if (i < BM) {
        g_tmin[i] = fenc(CUDART_INF_F);
        if ((i & 1) == 0) {
            float x0 = tgt[3 * i],     y0 = tgt[3 * i + 1], z0 = tgt[3 * i + 2];
            float x1 = tgt[3 * i + 3], y1 = tgt[3 * i + 4], z1 = tgt[3 * i + 5];
            float k0 = -0.5f * (x0 * x0 + y0 * y0 + z0 * z0);
            float k1 = -0.5f * (x1 * x1 + y1 * y1 + z1 * z1);
            g_ta[i >> 1] = make_float4(x0, x1, y0, y1);
            g_tb[i >> 1] = make_float4(z0, z1, k0, k1);
        }
    }
}

// ---------------------------------------------------------------------------
// Kernel 2: fused packed pass on e_ij = s.t - |s|^2/2 - |t|^2/2  (= -d/2).
// min d (both directions) == max e. Per 2 pairs: 1 add2 + 3 fma2 (fma pipe)
// + 4 FMNMX (alu pipe) -> 4 SMSP-cyc/pair on each pipe, balanced.
// Block = 256 threads = 16 target-groups (tx) x 16 source-groups (ty).
// Thread tile: 8 sources (persistent, broadcast-packed) x 8 targets/chunk
// (4 genuine f32x2 pairs loaded via LDG.128 from the SoA-paired layout).
// ---------------------------------------------------------------------------
__global__ void __launch_bounds__(256, 2)
chamfer_main(int N, int M) {
    const int b    = blockIdx.y;
    const int sblk = blockIdx.x;
    const int tid  = threadIdx.x;
    const int tx   = tid >> 4;    // target group 0..15
    const int ty   = tid & 15;    // source group 0..15 (consecutive lanes)

    const float4* __restrict__ S  = g_srcp + (size_t)b * N + sblk * SBLK;
    const float4* __restrict__ TA = g_ta + (size_t)b * (M / 2);
    const float4* __restrict__ TB = g_tb + (size_t)b * (M / 2);

    u64 sx2[8], sy2[8], sz2[8], sk2[8];
    float smax[8];
#pragma unroll
    for (int i = 0; i < 8; i++) {
        float4 v = S[ty * 8 + i];
        sx2[i] = pack2(v.x, v.x);
        sy2[i] = pack2(v.y, v.y);
        sz2[i] = pack2(v.z, v.z);
        sk2[i] = pack2(v.w, v.w);
        smax[i] = -CUDART_INF_F;
    }

    for (int c = 0; c < M; c += 128) {
        const int pbase = (c >> 1) + tx * 4;
        float tmax[8];
#pragma unroll
        for (int j = 0; j < 8; j++) tmax[j] = -CUDART_INF_F;

#pragma unroll
        for (int jp = 0; jp < 4; jp++) {
            float4 a  = TA[pbase + jp];
            float4 bb = TB[pbase + jp];
            u64 px2 = pack2(a.x, a.y);
            u64 py2 = pack2(a.z, a.w);
            u64 pz2 = pack2(bb.x, bb.y);
            u64 pk2 = pack2(bb.z, bb.w);
#pragma unroll
            for (int i = 0; i < 8; i++) {
                u64 kij = add2_(sk2[i], pk2);
                u64 e2  = fma2_(sx2[i], px2,
                          fma2_(sy2[i], py2,
                          fma2_(sz2[i], pz2, kij)));
                float elo, ehi;
                unpack2(e2, elo, ehi);
                smax[i]        = fmaxf(smax[i], fmaxf(elo, ehi));
                tmax[2 * jp]   = fmaxf(tmax[2 * jp], elo);
                tmax[2 * jp + 1] = fmaxf(tmax[2 * jp + 1], ehi);
            }
        }

        // Reduce tmax over the 16 consecutive ty-lanes (half warp), flush.
#pragma unroll
        for (int j = 0; j < 8; j++) {
            float v = tmax[j];
            v = fmaxf(v, __shfl_xor_sync(0xffffffffu, v, 8, 16));
            v = fmaxf(v, __shfl_xor_sync(0xffffffffu, v, 4, 16));
            v = fmaxf(v, __shfl_xor_sync(0xffffffffu, v, 2, 16));
            v = fmaxf(v, __shfl_xor_sync(0xffffffffu, v, 1, 16));
            if (ty == 0) {
                float d = -2.0f * v;
                atomicMin(&g_tmin[(size_t)b * M + c + tx * 8 + j], fenc(d));
            }
        }
    }

    // Finalize source mins: d_i = -2*smax_i, reduce across 16 tx slices, sum.
    __shared__ float red[16][136];
#pragma unroll
    for (int i = 0; i < 8; i++) red[tx][ty * 8 + i] = -2.0f * smax[i];
    __syncthreads();

    __shared__ float partial[128];
    if (tid < 128) {
        float m = red[0][tid];
#pragma unroll
        for (int k = 1; k < 16; k++) m = fminf(m, red[k][tid]);
        partial[tid] = m;
    }
    __syncthreads();
    if (tid < 64) partial[tid] += partial[tid + 64];
    __syncthreads();
    if (tid < 32) {
        float v = partial[tid] + partial[tid + 32];
#pragma unroll
        for (int o = 16; o > 0; o >>= 1)
            v += __shfl_down_sync(0xffffffffu, v, o);
        if (tid == 0) g_ssum[b * gridDim.x + sblk] = v;  // deterministic
    }
}

// ---------------------------------------------------------------------------
// Kernel 3: deterministic final reduction. One block per batch.
// ---------------------------------------------------------------------------
__global__ void chamfer_finish(float* __restrict__ out, int N, int M, int nsblk) {
    const int b   = blockIdx.x;
    const int tid = threadIdx.x;  // 256 threads

    float ts = 0.0f;
    for (int i = tid; i < M; i += 256)
        ts += fdec(g_tmin[(size_t)b * M + i]);
    float ss = 0.0f;
    for (int i = tid; i < nsblk; i += 256)
        ss += g_ssum[b * nsblk + i];

    __shared__ float s1[256], s2[256];
    s1[tid] = ts; s2[tid] = ss;
    __syncthreads();
    for (int o = 128; o > 0; o >>= 1) {
        if (tid < o) { s1[tid] += s1[tid + o]; s2[tid] += s2[tid + o]; }
        __syncthreads();
    }
    if (tid == 0) out[b] = s1[0] / (float)M + s2[0] / (float)N;
}

// ---------------------------------------------------------------------------
extern "C" void kernel_launch(void* const* d_in, const int* in_sizes, int n_in,
                              void* d_out, int out_size) {
    const float* src = (const float*)d_in[0];
    const float* tgt = (const float*)d_in[1];
    float* out = (float*)d_out;

    const int B = out_size;                 // 8
    const int N = in_sizes[0] / (3 * B);    // 8192
    const int M = in_sizes[1] / (3 * B);    // 8192
    const int BN = B * N, BM = B * M;
    const int total = BN > BM ? BN : BM;

    chamfer_prep<<<(total + 255) / 256, 256>>>(src, tgt, BN, BM);

    dim3 grid(N / SBLK, B);
    chamfer_main<<<grid, 256>>>(N, M);

    chamfer_finish<<<B, 256>>>(out, N, M, N / SBLK);
}

// round 3
// speedup vs baseline: 1.3673x; 1.2138x over previous
#include <cuda_runtime.h>
#include <math_constants.h>

// Problem constants (fixed by the dataset): B=8, N=M=8192, 3-D points.
#define MAXB 8
#define MAXN 8192
#define MAXM 8192
#define SBLK 128            // sources per block
#define NSBLK (MAXN / SBLK) // 64 source blocks per batch

typedef unsigned long long u64;

// Static scratch (allocation-free rule).
__device__ float4       g_srcp[MAXB * MAXN];      // {x, y, z, -0.5|s|^2}
__device__ float4       g_ta[MAXB * MAXM / 2];    // {x0, x1, y0, y1} per target pair
__device__ float4       g_tb[MAXB * MAXM / 2];    // {z0, z1, k0, k1} per target pair
__device__ unsigned int g_tmin[MAXB * MAXM];      // monotonic-encoded min distance
__device__ float        g_ssum[MAXB * NSBLK];

// ---- f32x2 packed math (FFMA2/FADD2 — PTX-only on sm_103a) --------------
__device__ __forceinline__ u64 pack2(float lo, float hi) {
    u64 r; asm("mov.b64 %0,{%1,%2};" : "=l"(r) : "f"(lo), "f"(hi)); return r;
}
__device__ __forceinline__ void unpack2(u64 v, float& lo, float& hi) {
    asm("mov.b64 {%0,%1},%2;" : "=f"(lo), "=f"(hi) : "l"(v));
}
__device__ __forceinline__ u64 fma2_(u64 a, u64 b, u64 c) {
    u64 d; asm("fma.rn.f32x2 %0,%1,%2,%3;" : "=l"(d) : "l"(a), "l"(b), "l"(c)); return d;
}
__device__ __forceinline__ u64 add2_(u64 a, u64 b) {
    u64 d; asm("add.rn.f32x2 %0,%1,%2;" : "=l"(d) : "l"(a), "l"(b)); return d;
}

// ---- monotonic float<->uint encoding (atomicMin-safe for any sign) ------
__device__ __forceinline__ unsigned fenc(float f) {
    unsigned b = __float_as_uint(f);
    return (b & 0x80000000u) ? ~b : (b | 0x80000000u);
}
__device__ __forceinline__ float fdec(unsigned k) {
    return __uint_as_float((k & 0x80000000u) ? (k & 0x7fffffffu) : ~k);
}

// ---------------------------------------------------------------------------
// Kernel 1: pack sources {x,y,z,-|s|^2/2}, target PAIRS into f32x2 SoA,
// init tmin to encoded +inf.
// ---------------------------------------------------------------------------
__global__ void chamfer_prep(const float* __restrict__ src,
                             const float* __restrict__ tgt,
                             int BN, int BM) {
    int i = blockIdx.x * blockDim.x + threadIdx.x;
    if (i < BN) {
        float x = src[3 * i], y = src[3 * i + 1], z = src[3 * i + 2];
        float k = -0.5f * (x * x + y * y + z * z);
        g_srcp[i] = make_float4(x, y, z, k);
    }
    if (i < BM) {
        g_tmin[i] = fenc(CUDART_INF_F);
        if ((i & 1) == 0) {
            float x0 = tgt[3 * i],     y0 = tgt[3 * i + 1], z0 = tgt[3 * i + 2];
            float x1 = tgt[3 * i + 3], y1 = tgt[3 * i + 4], z1 = tgt[3 * i + 5];
            float k0 = -0.5f * (x0 * x0 + y0 * y0 + z0 * z0);
            float k1 = -0.5f * (x1 * x1 + y1 * y1 + z1 * z1);
            g_ta[i >> 1] = make_float4(x0, x1, y0, y1);
            g_tb[i >> 1] = make_float4(z0, z1, k0, k1);
        }
    }
}

// ---------------------------------------------------------------------------
// Kernel 2: fused packed pass on e = s.t - |s|^2/2 - |t|^2/2 (= -d/2);
// min d both directions == max e.
// Block = 128 threads = 16 target-groups (tx) x 8 source-groups (ty).
// Thread tile: 16 sources persistent (packed source-pairs, 8 u64/coord)
// x 8 targets per 128-target chunk (targets broadcast-packed on the fly).
// Single wave: 512 CTAs at occupancy 4 on 148 SMs.
// ---------------------------------------------------------------------------
__global__ void __launch_bounds__(128, 4)
chamfer_main(int N, int M) {
    const int b    = blockIdx.y;
    const int sblk = blockIdx.x;
    const int tid  = threadIdx.x;
    const int tx   = tid >> 3;    // target group 0..15
    const int ty   = tid & 7;     // source group 0..7 (consecutive lanes)

    const float4* __restrict__ S  = g_srcp + (size_t)b * N + sblk * SBLK;
    const float4* __restrict__ TA = g_ta + (size_t)b * (M / 2);
    const float4* __restrict__ TB = g_tb + (size_t)b * (M / 2);

    // 16 persistent sources as 8 packed pairs per coordinate.
    u64 sx2[8], sy2[8], sz2[8], sk2[8];
    float smax[16];
#pragma unroll
    for (int i = 0; i < 8; i++) {
        float4 v0 = S[ty * 16 + 2 * i];
        float4 v1 = S[ty * 16 + 2 * i + 1];
        sx2[i] = pack2(v0.x, v1.x);
        sy2[i] = pack2(v0.y, v1.y);
        sz2[i] = pack2(v0.z, v1.z);
        sk2[i] = pack2(v0.w, v1.w);
        smax[2 * i] = -CUDART_INF_F;
        smax[2 * i + 1] = -CUDART_INF_F;
    }

    const int pb = tx * 4;               // this thread's pair offset in a chunk
    float4 ca = TA[pb], cb = TB[pb];     // current target-pair registers

    for (int c = 0; c < M; c += 128) {
        float tmax[8];
#pragma unroll
        for (int j = 0; j < 8; j++) tmax[j] = -CUDART_INF_F;

#pragma unroll
        for (int jp = 0; jp < 4; jp++) {
            // Prefetch next target pair (next jp, or next chunk's jp=0).
            int nidx;
            if (jp < 3)              nidx = (c >> 1) + pb + jp + 1;
            else if (c + 128 < M)    nidx = ((c + 128) >> 1) + pb;
            else                     nidx = (c >> 1) + pb;   // harmless reload
            float4 na = TA[nidx];
            float4 nb = TB[nidx];

            // Two targets in this pair: t=0 -> (ca.x, ca.z, cb.x, cb.z),
            //                           t=1 -> (ca.y, ca.w, cb.y, cb.w)
#pragma unroll
            for (int t = 0; t < 2; t++) {
                u64 tx2 = pack2(t ? ca.y : ca.x, t ? ca.y : ca.x);
                u64 ty2 = pack2(t ? ca.w : ca.z, t ? ca.w : ca.z);
                u64 tz2 = pack2(t ? cb.y : cb.x, t ? cb.y : cb.x);
                u64 tk2 = pack2(t ? cb.w : cb.z, t ? cb.w : cb.z);
                float tm = -CUDART_INF_F;
#pragma unroll
                for (int i = 0; i < 8; i++) {
                    u64 e2 = fma2_(sx2[i], tx2,
                             fma2_(sy2[i], ty2,
                             fma2_(sz2[i], tz2, add2_(sk2[i], tk2))));
                    float elo, ehi;
                    unpack2(e2, elo, ehi);
                    smax[2 * i]     = fmaxf(smax[2 * i], elo);
                    smax[2 * i + 1] = fmaxf(smax[2 * i + 1], ehi);
                    tm = fmaxf(tm, fmaxf(elo, ehi));
                }
                tmax[2 * jp + t] = tm;
            }
            ca = na; cb = nb;
        }

        // Reduce tmax over the 8 consecutive ty-lanes, flush to global.
#pragma unroll
        for (int j = 0; j < 8; j++) {
            float v = tmax[j];
            v = fmaxf(v, __shfl_xor_sync(0xffffffffu, v, 4, 8));
            v = fmaxf(v, __shfl_xor_sync(0xffffffffu, v, 2, 8));
            v = fmaxf(v, __shfl_xor_sync(0xffffffffu, v, 1, 8));
            if (ty == 0) {
                atomicMin(&g_tmin[(size_t)b * M + c + tx * 8 + j],
                          fenc(-2.0f * v));
            }
        }
    }

    // Finalize source mins: d_i = -2*smax_i, min across 16 tx slices, sum.
    __shared__ float red[16][136];
#pragma unroll
    for (int i = 0; i < 16; i++) red[tx][ty * 16 + i] = -2.0f * smax[i];
    __syncthreads();

    float m = red[0][tid];
#pragma unroll
    for (int k = 1; k < 16; k++) m = fminf(m, red[k][tid]);

    __shared__ float partial[128];
    partial[tid] = m;
    __syncthreads();
    if (tid < 64) partial[tid] += partial[tid + 64];
    __syncthreads();
    if (tid < 32) {
        float v = partial[tid] + partial[tid + 32];
#pragma unroll
        for (int o = 16; o > 0; o >>= 1)
            v += __shfl_down_sync(0xffffffffu, v, o);
        if (tid == 0) g_ssum[b * gridDim.x + sblk] = v;  // deterministic
    }
}

// ---------------------------------------------------------------------------
// Kernel 3: deterministic final reduction. One block per batch.
// ---------------------------------------------------------------------------
__global__ void chamfer_finish(float* __restrict__ out, int N, int M, int nsblk) {
    const int b   = blockIdx.x;
    const int tid = threadIdx.x;  // 256 threads

    float ts = 0.0f;
    for (int i = tid; i < M; i += 256)
        ts += fdec(g_tmin[(size_t)b * M + i]);
    float ss = 0.0f;
    for (int i = tid; i < nsblk; i += 256)
        ss += g_ssum[b * nsblk + i];

    __shared__ float s1[256], s2[256];
    s1[tid] = ts; s2[tid] = ss;
    __syncthreads();
    for (int o = 128; o > 0; o >>= 1) {
        if (tid < o) { s1[tid] += s1[tid + o]; s2[tid] += s2[tid + o]; }
        __syncthreads();
    }
    if (tid == 0) out[b] = s1[0] / (float)M + s2[0] / (float)N;
}

// ---------------------------------------------------------------------------
extern "C" void kernel_launch(void* const* d_in, const int* in_sizes, int n_in,
                              void* d_out, int out_size) {
    const float* src = (const float*)d_in[0];
    const float* tgt = (const float*)d_in[1];
    float* out = (float*)d_out;

    const int B = out_size;                 // 8
    const int N = in_sizes[0] / (3 * B);    // 8192
    const int M = in_sizes[1] / (3 * B);    // 8192
    const int BN = B * N, BM = B * M;
    const int total = BN > BM ? BN : BM;

    chamfer_prep<<<(total + 255) / 256, 256>>>(src, tgt, BN, BM);

    dim3 grid(N / SBLK, B);
    chamfer_main<<<grid, 128>>>(N, M);

    chamfer_finish<<<B, 256>>>(out, N, M, N / SBLK);
}